// round 11
// baseline (speedup 1.0000x reference)
#include <cuda_runtime.h>

#define NB     2048
#define NOH    20
#define NOTH   23
#define NC     10
#define SC     200      // NOH*NC
#define EMB    9
#define OUTC   32
#define XSTR   43       // NOH + NOTH
#define HW     2304     // 48*48
#define SLABSZ 73728    // OUTC*HW floats per batch

#define THREADS 256

// Single fused kernel, R3-replicator concurrency shape.
// Grid (mtile 18, c 8, bg 8) = 1152 CTAs x 256 threads, ~8 CTAs/SM.
// Each CTA: fold weights, compute the <=128 embedding rows its m-tile needs,
// compute its 128-m x 32-channel tile (16 KB), then store it for 32 batches
// b = c + 8*(bg*32 + u)  (512 KB stored per CTA — same as R3's replicator).
//
// Verified identities (rel_err ~1.4e-7, R1-R10):
//   out[b][o][m] depends on b only through c = b & 7
//   three 1x1 convs fold into one 32x32 weight W + bias cb
//   slab[c][o][m] = cb[o] + sum_i W[o,i]  * v[256*((c+i)&7)+q, r]  (q=m/9, r=m%9)
//                         + sum_j W[o,9+j]* x[bb_j*43+20+(4j+m)%23],
//                           bb_j = (256c + (2304j+m)/23) & 2047
__global__ void __launch_bounds__(THREADS) k_all(
    const float* __restrict__ x,
    const float* __restrict__ fc_w, const float* __restrict__ fc_b,
    const float* __restrict__ oh_w, const float* __restrict__ oh_b,
    const float* __restrict__ ot_w, const float* __restrict__ ot_b,
    const float* __restrict__ all_w, const float* __restrict__ all_b,
    float* __restrict__ out)
{
    __shared__ __align__(16) float s_W[OUTC * 32];     // fused weight, 4 KB
    __shared__ float s_cb[OUTC];
    __shared__ float s_v[8][16][EMB];                  // needed embedding rows
    __shared__ __align__(16) float s_out[OUTC * 128];  // 16 KB tile [o][m_local]

    const int t     = threadIdx.x;       // 0..255
    const int mtile = blockIdx.x;        // 0..17
    const int c     = blockIdx.y;        // 0..7
    const int bg    = blockIdx.z;        // 0..7

    // ---- fold weights: 4 entries per thread --------------------------------
    #pragma unroll
    for (int k = 0; k < 4; k++) {
        int idx = t + 256 * k;
        int o = idx >> 5, i = idx & 31;
        float s = 0.f;
        if (i < EMB) {
            #pragma unroll
            for (int cc = 0; cc < EMB; cc++)
                s += all_w[o * 32 + cc] * oh_w[cc * EMB + i];
        } else {
            int j = i - EMB;
            #pragma unroll
            for (int cc = 0; cc < NOTH; cc++)
                s += all_w[o * 32 + EMB + cc] * ot_w[cc * NOTH + j];
        }
        s_W[idx] = s;
    }
    if (t < OUTC) {
        float cb = all_b[t];
        #pragma unroll
        for (int cc = 0; cc < EMB; cc++)  cb += all_w[t * 32 + cc] * oh_b[cc];
        #pragma unroll
        for (int cc = 0; cc < NOTH; cc++) cb += all_w[t * 32 + EMB + cc] * ot_b[cc];
        s_cb[t] = cb;
    }

    // ---- embedding rows needed by this m-tile (<=128 rows, 1 per thread) ---
    // fc_w read directly from gmem/L2 (7.2 KB, chip-hot after first touches).
    const int m0 = mtile * 128;
    const int q0 = m0 / 9;
    const int nq = (m0 + 127) / 9 - q0 + 1;   // <= 16

    if (t < 8 * nq) {
        int k  = t / nq;
        int ql = t - k * nq;
        int b  = 256 * k + q0 + ql;
        const float* xr = x + b * XSTR;       // 20 consecutive floats
        float acc[EMB];
        #pragma unroll
        for (int e = 0; e < EMB; e++) acc[e] = fc_b[e];
        #pragma unroll
        for (int j = 0; j < NOH; j++) {
            int id   = (int)xr[j];
            int base = j * NC + id;
            #pragma unroll
            for (int e = 0; e < EMB; e++) acc[e] += fc_w[e * SC + base];
        }
        #pragma unroll
        for (int e = 0; e < EMB; e++) s_v[k][ql][e] = acc[e];
    }
    __syncthreads();    // s_W, s_cb, s_v ready

    // ---- compute tile: thread -> (m_local = t&127, 16 channels) ------------
    {
        const int ml = t & 127;
        const int o0 = (t >> 7) * 16;         // 0 or 16
        const int m  = m0 + ml;
        const int q  = m / 9;
        const int r  = m - 9 * q;
        const int ql = q - q0;

        float g[32];
        #pragma unroll
        for (int i = 0; i < 9; i++)
            g[i] = s_v[(c + i) & 7][ql][r];
        #pragma unroll
        for (int j = 0; j < 23; j++) {
            int eo = (4 * j + m) % 23;
            int T  = (2304 * j + m) / 23;
            int bb = (256 * c + T) & 2047;
            g[9 + j] = x[bb * XSTR + NOH + eo];
        }

        #pragma unroll
        for (int chn = 0; chn < 16; chn++) {
            int o = o0 + chn;
            const float4* W4 = (const float4*)(s_W + o * 32);
            float s = s_cb[o];
            #pragma unroll
            for (int j4 = 0; j4 < 8; j4++) {
                float4 w = W4[j4];
                s += w.x * g[4 * j4]     + w.y * g[4 * j4 + 1]
                   + w.z * g[4 * j4 + 2] + w.w * g[4 * j4 + 3];
            }
            s_out[o * 128 + ml] = s;
        }
    }
    __syncthreads();    // tile ready (4096 floats = 1024 float4)

    // ---- stage 4 float4 per thread -----------------------------------------
    const float4* so4 = (const float4*)s_out;
    const float4 v0 = so4[t];
    const float4 v1 = so4[t + 256];
    const float4 v2 = so4[t + 512];
    const float4 v3 = so4[t + 768];

    // float4 index f -> o = f>>5, ml4 = f&31 ; out offset o*(HW/4) + ml4
    const size_t off0 = (size_t)((t      ) >> 5) * (HW / 4) + ((t      ) & 31);
    const size_t off1 = (size_t)((t + 256) >> 5) * (HW / 4) + ((t + 256) & 31);
    const size_t off2 = (size_t)((t + 512) >> 5) * (HW / 4) + ((t + 512) & 31);
    const size_t off3 = (size_t)((t + 768) >> 5) * (HW / 4) + ((t + 768) & 31);

    float4* __restrict__ base = (float4*)out
        + (size_t)c * (SLABSZ / 4) + (size_t)(m0 >> 2);

    // stagger batch order per CTA inside its 32-batch group
    const int cta   = mtile + 18 * (c + 8 * bg);
    const int start = (cta * 13) & 31;        // odd -> bijection mod 32

    #pragma unroll 4
    for (int vv = 0; vv < 32; vv++) {
        int u = bg * 32 + ((vv + start) & 31);    // b = c + 8u
        float4* __restrict__ dst = base + (size_t)u * (8 * SLABSZ / 4);
        dst[off0] = v0;
        dst[off1] = v1;
        dst[off2] = v2;
        dst[off3] = v3;
    }
}

// ---------------------------------------------------------------------------
extern "C" void kernel_launch(void* const* d_in, const int* in_sizes, int n_in,
                              void* d_out, int out_size) {
    const float* x     = (const float*)d_in[0];
    const float* fc_w  = (const float*)d_in[1];
    const float* fc_b  = (const float*)d_in[2];
    const float* oh_w  = (const float*)d_in[3];
    const float* oh_b  = (const float*)d_in[4];
    const float* ot_w  = (const float*)d_in[5];
    const float* ot_b  = (const float*)d_in[6];
    const float* all_w = (const float*)d_in[7];
    const float* all_b = (const float*)d_in[8];
    float* out = (float*)d_out;

    dim3 grid(18, 8, 8);   // 1152 CTAs, ~8 CTAs/SM (R3 replicator shape)
    k_all<<<grid, THREADS>>>(x, fc_w, fc_b, oh_w, oh_b, ot_w, ot_b,
                             all_w, all_b, out);
}

// round 12
// speedup vs baseline: 1.0110x; 1.0110x over previous
#include <cuda_runtime.h>

#define NB     2048
#define NOH    20
#define NOTH   23
#define NC     10
#define SC     200      // NOH*NC
#define EMB    9
#define OUTC   32
#define XSTR   43       // NOH + NOTH
#define HW     2304     // 48*48
#define SLABSZ 73728    // OUTC*HW floats per batch

// Device scratch (allocation-free)
__device__ float g_slab[8 * SLABSZ];     // the 8 unique output slabs (2.36 MB)

// ---------------------------------------------------------------------------
// k_pre: compute the 8 unique slabs, wide-parallel shape.
// Grid (mtile 18, c 8, og2 4) = 576 CTAs x 256 threads (~4 CTAs/SM).
// Each CTA: fold 8 channels of the fused weight (1 entry/thread), compute the
// <=128 embedding rows its m-tile needs (1 row/thread, fc_w from L2), then
// each thread evaluates 4 channel-dots for one m position and writes g_slab.
//
// Verified identities (rel_err ~1.4e-7, R1-R11):
//   out[b][o][m] depends on b only through c = b & 7
//   three 1x1 convs fold into one 32x32 weight W + bias cb
//   slab[c][o][m] = cb[o] + sum_i W[o,i]  * v[256*((c+i)&7)+q, r]  (q=m/9, r=m%9)
//                         + sum_j W[o,9+j]* x[bb_j*43+20+(4j+m)%23],
//                           bb_j = (256c + (2304j+m)/23) & 2047
__global__ void __launch_bounds__(256) k_pre(
    const float* __restrict__ x,
    const float* __restrict__ fc_w, const float* __restrict__ fc_b,
    const float* __restrict__ oh_w, const float* __restrict__ oh_b,
    const float* __restrict__ ot_w, const float* __restrict__ ot_b,
    const float* __restrict__ all_w, const float* __restrict__ all_b)
{
    __shared__ __align__(16) float s_W[8 * 32];   // this CTA's 8 channels
    __shared__ float s_cb[8];
    __shared__ float s_v[8][16][EMB];             // needed embedding rows

    const int t      = threadIdx.x;    // 0..255
    const int mtile  = blockIdx.x;     // 0..17
    const int c      = blockIdx.y;     // 0..7
    const int o_base = blockIdx.z * 8; // 0,8,16,24

    // ---- fold this CTA's 8 channels: exactly 1 entry per thread ------------
    {
        const int o = o_base + (t >> 5);
        const int i = t & 31;
        float s = 0.f;
        if (i < EMB) {
            #pragma unroll
            for (int cc = 0; cc < EMB; cc++)
                s += all_w[o * 32 + cc] * oh_w[cc * EMB + i];
        } else {
            int j = i - EMB;
            #pragma unroll
            for (int cc = 0; cc < NOTH; cc++)
                s += all_w[o * 32 + EMB + cc] * ot_w[cc * NOTH + j];
        }
        s_W[t] = s;                    // t == (t>>5)*32 + (t&31)
    }
    if (t < 8) {
        const int o = o_base + t;
        float cb = all_b[o];
        #pragma unroll
        for (int cc = 0; cc < EMB; cc++)  cb += all_w[o * 32 + cc] * oh_b[cc];
        #pragma unroll
        for (int cc = 0; cc < NOTH; cc++) cb += all_w[o * 32 + EMB + cc] * ot_b[cc];
        s_cb[t] = cb;
    }

    // ---- embedding rows needed by this m-tile (1 row/thread, fc_w in L2) ---
    const int m0 = mtile * 128;
    const int q0 = m0 / 9;
    const int nq = (m0 + 127) / 9 - q0 + 1;   // <= 16

    if (t < 8 * nq) {
        int k  = t / nq;
        int ql = t - k * nq;
        int b  = 256 * k + q0 + ql;
        const float* xr = x + b * XSTR;
        float acc[EMB];
        #pragma unroll
        for (int e = 0; e < EMB; e++) acc[e] = fc_b[e];
        #pragma unroll
        for (int j = 0; j < NOH; j++) {
            int id   = (int)xr[j];
            int base = j * NC + id;
            #pragma unroll
            for (int e = 0; e < EMB; e++) acc[e] += fc_w[e * SC + base];
        }
        #pragma unroll
        for (int e = 0; e < EMB; e++) s_v[k][ql][e] = acc[e];
    }
    __syncthreads();

    // ---- per-thread: one m position, 4 of this CTA's 8 channels ------------
    const int ml  = t & 127;
    const int lo0 = (t >> 7) * 4;       // 0 or 4
    const int m   = m0 + ml;
    const int q   = m / 9;
    const int r   = m - 9 * q;
    const int ql  = q - q0;

    float g[32];
    #pragma unroll
    for (int i = 0; i < 9; i++)
        g[i] = s_v[(c + i) & 7][ql][r];
    #pragma unroll
    for (int j = 0; j < 23; j++) {
        int eo = (4 * j + m) % 23;
        int T  = (2304 * j + m) / 23;
        int bb = (256 * c + T) & 2047;
        g[9 + j] = x[bb * XSTR + NOH + eo];
    }

    float* dst = g_slab + (size_t)c * SLABSZ + m;
    #pragma unroll
    for (int chn = 0; chn < 4; chn++) {
        int lo = lo0 + chn;
        const float4* W4 = (const float4*)(s_W + lo * 32);
        float s = s_cb[lo];
        #pragma unroll
        for (int j4 = 0; j4 < 8; j4++) {
            float4 w = W4[j4];
            s += w.x * g[4 * j4]     + w.y * g[4 * j4 + 1]
               + w.z * g[4 * j4 + 2] + w.w * g[4 * j4 + 3];
        }
        dst[(size_t)(o_base + lo) * HW] = s;
    }
}

// ---------------------------------------------------------------------------
// k_rep: out[b][.] = slab[b%8][.] — byte-identical to the proven 90.0us/76.4%
// replicator from R3. Each CTA stages a 32 KB chunk in registers and stores
// it for 16 batches. grid = 8 c * 9 chunks * 16 bgroups = 1152 CTAs x 256 thr.
__global__ void __launch_bounds__(256) k_rep(float* __restrict__ out) {
    int bid = blockIdx.x;
    int c     = bid / 144;             // 0..7
    int rest  = bid % 144;
    int chunk = rest / 16;             // 0..8
    int bg    = rest % 16;             // 0..15
    int t = threadIdx.x;

    size_t chunk_off = (size_t)chunk * 8192;
    const float4* __restrict__ src =
        (const float4*)(g_slab + (size_t)c * SLABSZ + chunk_off);

    float4 r0 = src[0 * 256 + t];
    float4 r1 = src[1 * 256 + t];
    float4 r2 = src[2 * 256 + t];
    float4 r3 = src[3 * 256 + t];
    float4 r4 = src[4 * 256 + t];
    float4 r5 = src[5 * 256 + t];
    float4 r6 = src[6 * 256 + t];
    float4 r7 = src[7 * 256 + t];

#pragma unroll 4
    for (int u = 0; u < 16; u++) {
        int b = c + 8 * (bg * 16 + u);
        float4* __restrict__ dst = (float4*)(out + (size_t)b * SLABSZ + chunk_off);
        dst[0 * 256 + t] = r0;
        dst[1 * 256 + t] = r1;
        dst[2 * 256 + t] = r2;
        dst[3 * 256 + t] = r3;
        dst[4 * 256 + t] = r4;
        dst[5 * 256 + t] = r5;
        dst[6 * 256 + t] = r6;
        dst[7 * 256 + t] = r7;
    }
}

// ---------------------------------------------------------------------------
extern "C" void kernel_launch(void* const* d_in, const int* in_sizes, int n_in,
                              void* d_out, int out_size) {
    const float* x     = (const float*)d_in[0];
    const float* fc_w  = (const float*)d_in[1];
    const float* fc_b  = (const float*)d_in[2];
    const float* oh_w  = (const float*)d_in[3];
    const float* oh_b  = (const float*)d_in[4];
    const float* ot_w  = (const float*)d_in[5];
    const float* ot_b  = (const float*)d_in[6];
    const float* all_w = (const float*)d_in[7];
    const float* all_b = (const float*)d_in[8];
    float* out = (float*)d_out;

    dim3 pgrid(18, 8, 4);   // 576 CTAs, 4/SM — wide, shallow prologue
    k_pre<<<pgrid, 256>>>(x, fc_w, fc_b, oh_w, oh_b, ot_w, ot_b, all_w, all_b);
    k_rep<<<1152, 256>>>(out);
}

// round 13
// speedup vs baseline: 1.0149x; 1.0039x over previous
#include <cuda_runtime.h>

#define NB     2048
#define NOH    20
#define NOTH   23
#define NC     10
#define SC     200      // NOH*NC
#define EMB    9
#define OUTC   32
#define XSTR   43       // NOH + NOTH
#define HW     2304     // 48*48
#define SLABSZ 73728    // OUTC*HW floats per batch

// Device scratch (allocation-free)
__device__ float g_slab[8 * SLABSZ];     // the 8 unique output slabs (2.36 MB)

// ---------------------------------------------------------------------------
// k_pre: compute the 8 unique slabs. Grid (mtile 18, c 8, og2 4) = 576 CTAs
// x 256 threads. Each CTA: fold its 8 channels of the fused weight (1 entry/
// thread), compute the <=128 embedding rows its m-tile needs, evaluate
// 4 channel-dots per thread into an smem tile, then store the tile to g_slab
// fully coalesced (float4, 512B per warp-store — R12 wrote 9216B-strided
// scalars). Ends with griddepcontrol.launch_dependents to release k_rep.
//
// Verified identities (rel_err ~1.4e-7, R1-R12):
//   out[b][o][m] depends on b only through c = b & 7
//   three 1x1 convs fold into one 32x32 weight W + bias cb
//   slab[c][o][m] = cb[o] + sum_i W[o,i]  * v[256*((c+i)&7)+q, r]  (q=m/9, r=m%9)
//                         + sum_j W[o,9+j]* x[bb_j*43+20+(4j+m)%23],
//                           bb_j = (256c + (2304j+m)/23) & 2047
__global__ void __launch_bounds__(256) k_pre(
    const float* __restrict__ x,
    const float* __restrict__ fc_w, const float* __restrict__ fc_b,
    const float* __restrict__ oh_w, const float* __restrict__ oh_b,
    const float* __restrict__ ot_w, const float* __restrict__ ot_b,
    const float* __restrict__ all_w, const float* __restrict__ all_b)
{
    __shared__ __align__(16) float s_W[8 * 32];   // this CTA's 8 channels
    __shared__ float s_cb[8];
    __shared__ float s_v[8][16][EMB];             // needed embedding rows
    __shared__ __align__(16) float s_out[8 * 128];// 4 KB tile [lo][ml]

    const int t      = threadIdx.x;    // 0..255
    const int mtile  = blockIdx.x;     // 0..17
    const int c      = blockIdx.y;     // 0..7
    const int o_base = blockIdx.z * 8; // 0,8,16,24

    // ---- fold this CTA's 8 channels: 1 entry per thread --------------------
    {
        const int o = o_base + (t >> 5);
        const int i = t & 31;
        float s = 0.f;
        if (i < EMB) {
            #pragma unroll
            for (int cc = 0; cc < EMB; cc++)
                s += all_w[o * 32 + cc] * oh_w[cc * EMB + i];
        } else {
            int j = i - EMB;
            #pragma unroll
            for (int cc = 0; cc < NOTH; cc++)
                s += all_w[o * 32 + EMB + cc] * ot_w[cc * NOTH + j];
        }
        s_W[t] = s;
    }
    if (t < 8) {
        const int o = o_base + t;
        float cb = all_b[o];
        #pragma unroll
        for (int cc = 0; cc < EMB; cc++)  cb += all_w[o * 32 + cc] * oh_b[cc];
        #pragma unroll
        for (int cc = 0; cc < NOTH; cc++) cb += all_w[o * 32 + EMB + cc] * ot_b[cc];
        s_cb[t] = cb;
    }

    // ---- embedding rows needed by this m-tile (1 row/thread, fc_w in L2) ---
    const int m0 = mtile * 128;
    const int q0 = m0 / 9;
    const int nq = (m0 + 127) / 9 - q0 + 1;   // <= 16

    if (t < 8 * nq) {
        int k  = t / nq;
        int ql = t - k * nq;
        int b  = 256 * k + q0 + ql;
        const float* xr = x + b * XSTR;
        float acc[EMB];
        #pragma unroll
        for (int e = 0; e < EMB; e++) acc[e] = fc_b[e];
        #pragma unroll
        for (int j = 0; j < NOH; j++) {
            int id   = (int)xr[j];
            int base = j * NC + id;
            #pragma unroll
            for (int e = 0; e < EMB; e++) acc[e] += fc_w[e * SC + base];
        }
        #pragma unroll
        for (int e = 0; e < EMB; e++) s_v[k][ql][e] = acc[e];
    }
    __syncthreads();

    // ---- per-thread: one m position, 4 of this CTA's 8 channels ------------
    {
        const int ml  = t & 127;
        const int lo0 = (t >> 7) * 4;       // 0 or 4
        const int m   = m0 + ml;
        const int q   = m / 9;
        const int r   = m - 9 * q;
        const int ql  = q - q0;

        float g[32];
        #pragma unroll
        for (int i = 0; i < 9; i++)
            g[i] = s_v[(c + i) & 7][ql][r];
        #pragma unroll
        for (int j = 0; j < 23; j++) {
            int eo = (4 * j + m) % 23;
            int T  = (2304 * j + m) / 23;
            int bb = (256 * c + T) & 2047;
            g[9 + j] = x[bb * XSTR + NOH + eo];
        }

        #pragma unroll
        for (int chn = 0; chn < 4; chn++) {
            int lo = lo0 + chn;
            const float4* W4 = (const float4*)(s_W + lo * 32);
            float s = s_cb[lo];
            #pragma unroll
            for (int j4 = 0; j4 < 8; j4++) {
                float4 w = W4[j4];
                s += w.x * g[4 * j4]     + w.y * g[4 * j4 + 1]
                   + w.z * g[4 * j4 + 2] + w.w * g[4 * j4 + 3];
            }
            s_out[lo * 128 + ml] = s;
        }
    }
    __syncthreads();

    // ---- coalesced tile store: 256 float4, one per thread ------------------
    {
        const int lo  = t >> 5;             // 0..7
        const int ml4 = t & 31;             // float4 within row
        float4 v = ((const float4*)s_out)[t];
        float4* dst4 = (float4*)g_slab
            + (size_t)c * (SLABSZ / 4)
            + (size_t)(o_base + lo) * (HW / 4)
            + (m0 >> 2) + ml4;
        *dst4 = v;
    }

    // ---- release dependent grid (PDL) --------------------------------------
    __threadfence();
    __syncthreads();
    asm volatile("griddepcontrol.launch_dependents;" ::: "memory");
}

// ---------------------------------------------------------------------------
// k_rep: out[b][.] = slab[b%8][.] — the proven 89.8us/76.7% replicator.
// PDL: CTAs launch while k_pre runs, do index setup, then wait.
// grid = 8 c * 9 chunks * 16 bgroups = 1152 CTAs x 256 thr.
__global__ void __launch_bounds__(256) k_rep(float* __restrict__ out) {
    int bid = blockIdx.x;
    int c     = bid / 144;             // 0..7
    int rest  = bid % 144;
    int chunk = rest / 16;             // 0..8
    int bg    = rest % 16;             // 0..15
    int t = threadIdx.x;

    size_t chunk_off = (size_t)chunk * 8192;
    const float4* __restrict__ src =
        (const float4*)(g_slab + (size_t)c * SLABSZ + chunk_off);
    float4* __restrict__ out4 = (float4*)(out + chunk_off);

    // wait for k_pre's memory to be visible
    asm volatile("griddepcontrol.wait;" ::: "memory");

    float4 r0 = src[0 * 256 + t];
    float4 r1 = src[1 * 256 + t];
    float4 r2 = src[2 * 256 + t];
    float4 r3 = src[3 * 256 + t];
    float4 r4 = src[4 * 256 + t];
    float4 r5 = src[5 * 256 + t];
    float4 r6 = src[6 * 256 + t];
    float4 r7 = src[7 * 256 + t];

#pragma unroll 4
    for (int u = 0; u < 16; u++) {
        int b = c + 8 * (bg * 16 + u);
        float4* __restrict__ dst = out4 + (size_t)b * (SLABSZ / 4);
        dst[0 * 256 + t] = r0;
        dst[1 * 256 + t] = r1;
        dst[2 * 256 + t] = r2;
        dst[3 * 256 + t] = r3;
        dst[4 * 256 + t] = r4;
        dst[5 * 256 + t] = r5;
        dst[6 * 256 + t] = r6;
        dst[7 * 256 + t] = r7;
    }
}

// ---------------------------------------------------------------------------
extern "C" void kernel_launch(void* const* d_in, const int* in_sizes, int n_in,
                              void* d_out, int out_size) {
    const float* x     = (const float*)d_in[0];
    const float* fc_w  = (const float*)d_in[1];
    const float* fc_b  = (const float*)d_in[2];
    const float* oh_w  = (const float*)d_in[3];
    const float* oh_b  = (const float*)d_in[4];
    const float* ot_w  = (const float*)d_in[5];
    const float* ot_b  = (const float*)d_in[6];
    const float* all_w = (const float*)d_in[7];
    const float* all_b = (const float*)d_in[8];
    float* out = (float*)d_out;

    dim3 pgrid(18, 8, 4);   // 576 CTAs
    k_pre<<<pgrid, 256>>>(x, fc_w, fc_b, oh_w, oh_b, ot_w, ot_b, all_w, all_b);

    // k_rep with programmatic dependent launch: overlaps its launch/setup
    // with k_pre's tail; griddepcontrol.wait gates the g_slab reads.
    cudaLaunchConfig_t cfg = {};
    cfg.gridDim  = dim3(1152, 1, 1);
    cfg.blockDim = dim3(256, 1, 1);
    cfg.dynamicSmemBytes = 0;
    cfg.stream = 0;                     // legacy default stream (captured)
    cudaLaunchAttribute attrs[1];
    attrs[0].id = cudaLaunchAttributeProgrammaticStreamSerialization;
    attrs[0].val.programmaticStreamSerializationAllowed = 1;
    cfg.attrs = attrs;
    cfg.numAttrs = 1;
    cudaLaunchKernelEx(&cfg, k_rep, out);
}